// round 1
// baseline (speedup 1.0000x reference)
#include <cuda_runtime.h>
#include <math.h>

#define B_SZ 4
#define SEQ 2048
#define DM 1024
#define ST 16
#define MROWS (B_SZ * SEQ)   // 8192

// ---------------- scratch (__device__ globals; no allocation allowed) ----------------
__device__ float  g_delta[MROWS * DM];      // softplus(x@Wd+bd), 32 MB
__device__ float2 g_BC[MROWS * ST];         // (B, C) interleaved per (row, n), 1 MB
__device__ float  g_WT[32 * DM];            // rows 0-15: Wb^T, rows 16-31: Wc^T

// ---------------- prep: transpose Wb, Wc into g_WT ----------------
__global__ void prep_wt_kernel(const float* __restrict__ Wb, const float* __restrict__ Wc) {
    int i = blockIdx.x * blockDim.x + threadIdx.x;   // 0 .. 32767
    if (i < ST * DM) {
        int col = i & 15, k = i >> 4;
        g_WT[col * DM + k] = Wb[i];
    } else {
        int j = i - ST * DM;
        int col = j & 15, k = j >> 4;
        g_WT[(16 + col) * DM + k] = Wc[j];
    }
}

// ---------------- big GEMM: delta = softplus(X @ Wd + bd) ----------------
// X: [8192,1024], Wd: [1024,1024] (row-major, K x N), out g_delta [8192,1024]
#define BM 128
#define BN 128
#define BK 8
__global__ __launch_bounds__(256, 2)
void gemm_softplus_kernel(const float* __restrict__ X, const float* __restrict__ W,
                          const float* __restrict__ bias) {
    __shared__ float As[BK][BM];
    __shared__ float Bs[BK][BN];

    const int tid = threadIdx.x;                 // 0..255
    const int bm = blockIdx.y * BM;
    const int bn = blockIdx.x * BN;

    // A tile loader: 128 rows x 8 k, one float4 along k per thread
    const int arow = tid >> 1;
    const int acol = (tid & 1) * 4;
    // B tile loader: 8 rows x 128 n, one float4 along n per thread
    const int brow = tid >> 5;
    const int bcol = (tid & 31) * 4;

    const int tx = tid & 15;     // n-tile
    const int ty = tid >> 4;     // m-tile

    float acc[8][8];
#pragma unroll
    for (int i = 0; i < 8; ++i)
#pragma unroll
        for (int j = 0; j < 8; ++j) acc[i][j] = 0.f;

    for (int k0 = 0; k0 < DM; k0 += BK) {
        float4 av = *(const float4*)&X[(size_t)(bm + arow) * DM + k0 + acol];
        As[acol + 0][arow] = av.x;
        As[acol + 1][arow] = av.y;
        As[acol + 2][arow] = av.z;
        As[acol + 3][arow] = av.w;
        float4 bv = *(const float4*)&W[(size_t)(k0 + brow) * DM + bn + bcol];
        *(float4*)&Bs[brow][bcol] = bv;
        __syncthreads();

#pragma unroll
        for (int kk = 0; kk < BK; ++kk) {
            float4 a0 = *(const float4*)&As[kk][ty * 8];
            float4 a1 = *(const float4*)&As[kk][ty * 8 + 4];
            float4 b0 = *(const float4*)&Bs[kk][tx * 8];
            float4 b1 = *(const float4*)&Bs[kk][tx * 8 + 4];
            float ar[8] = {a0.x, a0.y, a0.z, a0.w, a1.x, a1.y, a1.z, a1.w};
            float br[8] = {b0.x, b0.y, b0.z, b0.w, b1.x, b1.y, b1.z, b1.w};
#pragma unroll
            for (int i = 0; i < 8; ++i)
#pragma unroll
                for (int j = 0; j < 8; ++j)
                    acc[i][j] = fmaf(ar[i], br[j], acc[i][j]);
        }
        __syncthreads();
    }

    // epilogue: + bias, softplus, store
    float bv[8];
#pragma unroll
    for (int j = 0; j < 8; ++j) bv[j] = bias[bn + tx * 8 + j];

#pragma unroll
    for (int i = 0; i < 8; ++i) {
        int m = bm + ty * 8 + i;
        float o[8];
#pragma unroll
        for (int j = 0; j < 8; ++j) {
            float z = acc[i][j] + bv[j];
            // stable softplus: max(z,0) + log1p(exp(-|z|))
            o[j] = fmaxf(z, 0.f) + log1pf(__expf(-fabsf(z)));
        }
        float* dst = &g_delta[(size_t)m * DM + bn + tx * 8];
        *(float4*)(dst)     = make_float4(o[0], o[1], o[2], o[3]);
        *(float4*)(dst + 4) = make_float4(o[4], o[5], o[6], o[7]);
    }
}

// ---------------- B/C projections: g_BC[row][n] = (x_row @ Wb + bb, x_row @ Wc + bc) ----------------
__global__ __launch_bounds__(128)
void bc_kernel(const float* __restrict__ x, const float* __restrict__ bb,
               const float* __restrict__ bc) {
    __shared__ float xs[DM];
    __shared__ float red[4][32];
    const int row = blockIdx.x;
    const int tid = threadIdx.x;   // 0..127

    const float4* xr = (const float4*)(x + (size_t)row * DM);
    ((float4*)xs)[tid]       = xr[tid];
    ((float4*)xs)[tid + 128] = xr[tid + 128];
    __syncthreads();

    const int o   = tid & 31;   // output id: 0-15 -> B, 16-31 -> C
    const int seg = tid >> 5;   // K-segment 0..3 (256 each)

    const float4* w  = (const float4*)(g_WT + o * DM + seg * 256);
    const float4* xv = (const float4*)(xs + seg * 256);
    float p = 0.f;
#pragma unroll 8
    for (int i = 0; i < 64; ++i) {
        float4 a = xv[i];
        float4 ww = w[i];
        p += a.x * ww.x + a.y * ww.y + a.z * ww.z + a.w * ww.w;
    }
    red[seg][o] = p;
    __syncthreads();

    if (tid < 32) {
        float s = red[0][tid] + red[1][tid] + red[2][tid] + red[3][tid];
        int col = tid & 15;
        float bias = (tid < 16) ? bb[col] : bc[col];
        float* out = (float*)g_BC;
        out[((size_t)row * ST + col) * 2 + (tid >> 4)] = s + bias;
    }
}

// ---------------- sequential scan: one thread per (b, d, n) ----------------
// warp = 2 d-lanes x 16 states; shfl_xor reduction over the 16 states.
__global__ __launch_bounds__(128)
void scan_kernel(const float* __restrict__ x, const float* __restrict__ A_log,
                 const float* __restrict__ D_skip, float* __restrict__ y) {
    const int gw   = blockIdx.x * (blockDim.x >> 5) + (threadIdx.x >> 5); // 0..2047
    const int lane = threadIdx.x & 31;
    const int half = lane >> 4;
    const int n    = lane & 15;

    const int b     = gw >> 9;          // 512 warps per batch
    const int dpair = gw & 511;
    const int d     = dpair * 2 + half;

    const float A   = -__expf(A_log[d * ST + n]);   // negative
    const float dsk = D_skip[d];

    const float*  xp  = x       + (size_t)b * SEQ * DM + d;
    const float*  dp  = g_delta + (size_t)b * SEQ * DM + d;
    const float2* bcp = g_BC    + (size_t)b * SEQ * ST + n;
    float*        yp  = y       + (size_t)b * SEQ * DM + d;

    float h = 0.f;
#pragma unroll 4
    for (int t = 0; t < SEQ; ++t) {
        float  xv = xp[(size_t)t * DM];
        float  dt = dp[(size_t)t * DM];
        float2 bcv = bcp[(size_t)t * ST];
        float  bar = __expf(dt * A);                 // in (0,1]
        h = fmaf(bar, h, dt * xv * bcv.x);
        float p = h * bcv.y;
        p += __shfl_xor_sync(0xffffffffu, p, 8);
        p += __shfl_xor_sync(0xffffffffu, p, 4);
        p += __shfl_xor_sync(0xffffffffu, p, 2);
        p += __shfl_xor_sync(0xffffffffu, p, 1);
        if (n == 0) yp[(size_t)t * DM] = fmaf(xv, dsk, p);
    }
}

// ---------------- launch ----------------
extern "C" void kernel_launch(void* const* d_in, const int* in_sizes, int n_in,
                              void* d_out, int out_size) {
    (void)in_sizes; (void)n_in; (void)out_size;
    const float* x     = (const float*)d_in[0];
    const float* A_log = (const float*)d_in[1];
    const float* Dsk   = (const float*)d_in[2];
    const float* Wd    = (const float*)d_in[3];
    const float* bd    = (const float*)d_in[4];
    const float* Wb    = (const float*)d_in[5];
    const float* bb    = (const float*)d_in[6];
    const float* Wc    = (const float*)d_in[7];
    const float* bc    = (const float*)d_in[8];
    float* y = (float*)d_out;

    prep_wt_kernel<<<32, 1024>>>(Wb, Wc);
    gemm_softplus_kernel<<<dim3(DM / BN, MROWS / BM), 256>>>(x, Wd, bd);
    bc_kernel<<<MROWS, 128>>>(x, bb, bc);
    scan_kernel<<<512, 128>>>(x, A_log, Dsk, y);
}